// round 4
// baseline (speedup 1.0000x reference)
#include <cuda_runtime.h>
#include <cuda_fp16.h>
#include <float.h>
#include <math.h>
#include <cstdint>

#define BB 8
#define NN 2048
#define DD 512

// ---------------------------------------------------------------------------
// Scratch (__device__ globals only — allocation-free contract)
// ---------------------------------------------------------------------------
__device__ float g_xx[BB * NN];
__device__ float g_dist[(size_t)BB * NN * NN];          // 134 MB
__device__ __half g_sp[2][(size_t)BB * NN * DD];        // h / l fp16 splits, 32 MB

__device__ __forceinline__ uint32_t smem_u32(const void* p) {
    uint32_t a;
    asm("{ .reg .u64 t; cvta.to.shared.u64 t, %1; cvt.u32.u64 %0, t; }" : "=r"(a) : "l"(p));
    return a;
}

#define LDSM4(r0, r1, r2, r3, addr) \
    asm volatile("ldmatrix.sync.aligned.m8n8.x4.shared.b16 {%0,%1,%2,%3}, [%4];" \
                 : "=r"(r0), "=r"(r1), "=r"(r2), "=r"(r3) : "r"(addr))

#define MMA16816(c, a, b0, b1) \
    asm volatile("mma.sync.aligned.m16n8k16.row.col.f32.f16.f16.f32 " \
                 "{%0,%1,%2,%3}, {%4,%5,%6,%7}, {%8,%9}, {%0,%1,%2,%3};" \
                 : "+f"((c)[0]), "+f"((c)[1]), "+f"((c)[2]), "+f"((c)[3]) \
                 : "r"((a)[0]), "r"((a)[1]), "r"((a)[2]), "r"((a)[3]), "r"(b0), "r"(b1))

#define CP_ASYNC16(dst, src) \
    asm volatile("cp.async.cg.shared.global [%0], [%1], 16;" :: "r"(dst), "l"(src))
#define CP_COMMIT() asm volatile("cp.async.commit_group;" ::: "memory")

// ---------------------------------------------------------------------------
// Kernel 0: fp16 2-word split of put  (x = h + l exactly to 2^-22)
// ---------------------------------------------------------------------------
__global__ __launch_bounds__(256) void split_kernel(const float* __restrict__ put) {
    size_t i4 = ((size_t)blockIdx.x * 256 + threadIdx.x) * 4;
    float4 v = *(const float4*)(put + i4);
    float x[4] = {v.x, v.y, v.z, v.w};
    __half h[4], l[4];
#pragma unroll
    for (int q = 0; q < 4; q++) {
        h[q] = __float2half(x[q]);
        l[q] = __float2half(x[q] - __half2float(h[q]));
    }
    *(uint2*)(&g_sp[0][i4]) = *(uint2*)h;
    *(uint2*)(&g_sp[1][i4]) = *(uint2*)l;
}

// ---------------------------------------------------------------------------
// Kernel 1: row squared norms (fp32 exact)
// ---------------------------------------------------------------------------
__global__ __launch_bounds__(256) void xx_kernel(const float* __restrict__ put) {
    int row  = blockIdx.x * 8 + (threadIdx.x >> 5);
    int lane = threadIdx.x & 31;
    const float* p = put + (size_t)row * DD;
    float s = 0.f;
#pragma unroll
    for (int f = 0; f < 4; f++) {
        float4 v = *(const float4*)(p + f * 128 + lane * 4);
        s = fmaf(v.x, v.x, s); s = fmaf(v.y, v.y, s);
        s = fmaf(v.z, v.z, s); s = fmaf(v.w, v.w, s);
    }
#pragma unroll
    for (int off = 16; off; off >>= 1) s += __shfl_xor_sync(0xffffffffu, s, off);
    if (lane == 0) g_xx[row] = s;
}

// ---------------------------------------------------------------------------
// Kernel 2: distance tiles via classic mma.sync fp16 3-pass split GEMM.
// 128x128 tile, BK=32, cp.async double buffer, triangular grid + mirror.
// ---------------------------------------------------------------------------
#define PITCH_H 40                       // halves per smem row (pad: conflict-free)
#define TILE_B  (128 * PITCH_H * 2)      // 10240 B per tile
#define BUF_B   (4 * TILE_B)             // Ah Al Bh Bl
#define XX_OFF  (2 * BUF_B)              // 81920
#define SM_TOTAL (XX_OFF + 1024)
#define T_PITCH 136                      // f32 pitch for transpose staging

__global__ __launch_bounds__(256, 1) void dist_mma_kernel() {
    int bx = blockIdx.x, by = blockIdx.y, b = blockIdx.z;
    if (by > bx) return;
    bool diag = (bx == by);

    extern __shared__ char smem[];
    uint32_t sbase = smem_u32(smem);
    int tid  = threadIdx.x;
    int lane = tid & 31;
    int wid  = tid >> 5;

    int j0 = by * 128, i0 = bx * 128, bofs = b * NN;

    float* xxA = (float*)(smem + XX_OFF);
    float* xxB = (float*)(smem + XX_OFF + 512);
    if (tid < 128) {
        xxA[tid] = g_xx[bofs + j0 + tid];
        xxB[tid] = g_xx[bofs + i0 + tid];
    }

    // ---- cp.async fill: 2048 16B chunks per buffer, 8 per thread ----
    int fr   = (tid >> 2);        // 0..63
    int fck  = tid & 3;           // 16B chunk within row
    auto fill = [&](int buf, int kt) {
#pragma unroll
        for (int q = 0; q < 8; q++) {
            int rr   = fr + 64 * (q & 1);         // row 0..127
            int tile = q >> 1;                    // 0:Ah 1:Al 2:Bh 3:Bl
            int word = tile & 1;
            int grow = (tile < 2 ? j0 : i0) + rr;
            const __half* src = &g_sp[word][(size_t)(bofs + grow) * DD + kt * 32 + fck * 8];
            uint32_t dst = sbase + buf * BUF_B + tile * TILE_B + rr * (PITCH_H * 2) + fck * 16;
            CP_ASYNC16(dst, src);
        }
    };

    // warp tiling: 2 (M) x 4 (N) warps; each warp 64x32
    int wm = (wid >> 2) * 64;
    int wn = (wid & 3) * 32;

    float acc[4][4][4];
#pragma unroll
    for (int im = 0; im < 4; im++)
#pragma unroll
        for (int in = 0; in < 4; in++)
#pragma unroll
            for (int q = 0; q < 4; q++) acc[im][in][q] = 0.f;

    fill(0, 0);
    CP_COMMIT();

    int arow = lane & 15;
    int acol = (lane >> 4) * 8;
    int brow = (lane & 7) + ((lane >> 4) << 3);
    int bcol = ((lane >> 3) & 1) * 8;

    for (int kt = 0; kt < 16; kt++) {
        if (kt < 15) { fill((kt + 1) & 1, kt + 1); CP_COMMIT(); }
        if (kt < 15) asm volatile("cp.async.wait_group 1;" ::: "memory");
        else         asm volatile("cp.async.wait_group 0;" ::: "memory");
        __syncthreads();

        uint32_t base = sbase + (kt & 1) * BUF_B;
#pragma unroll
        for (int kc = 0; kc < 2; kc++) {
            int kofs = kc * 16;
            uint32_t ah[4][4], al[4][4];
#pragma unroll
            for (int im = 0; im < 4; im++) {
                uint32_t off = (uint32_t)((wm + im * 16 + arow) * (PITCH_H * 2) + (kofs + acol) * 2);
                LDSM4(ah[im][0], ah[im][1], ah[im][2], ah[im][3], base + 0 * TILE_B + off);
                LDSM4(al[im][0], al[im][1], al[im][2], al[im][3], base + 1 * TILE_B + off);
            }
            uint32_t bh[8], bl[8];
#pragma unroll
            for (int bp = 0; bp < 2; bp++) {
                uint32_t off = (uint32_t)((wn + bp * 16 + brow) * (PITCH_H * 2) + (kofs + bcol) * 2);
                LDSM4(bh[bp*4+0], bh[bp*4+1], bh[bp*4+2], bh[bp*4+3], base + 2 * TILE_B + off);
                LDSM4(bl[bp*4+0], bl[bp*4+1], bl[bp*4+2], bl[bp*4+3], base + 3 * TILE_B + off);
            }
#pragma unroll
            for (int im = 0; im < 4; im++)
#pragma unroll
                for (int in = 0; in < 4; in++) {
                    MMA16816(acc[im][in], ah[im], bh[in*2], bh[in*2+1]);   // h*h
                    MMA16816(acc[im][in], ah[im], bl[in*2], bl[in*2+1]);   // h*l
                    MMA16816(acc[im][in], al[im], bh[in*2], bh[in*2+1]);   // l*h
                }
        }
        __syncthreads();
    }

    // ---- epilogue: dist + normal store + (mirror via smem transpose) ----
    float* smemT = (float*)smem;     // [128][T_PITCH] overlay (69.6 KB < 81.9 KB)

#pragma unroll
    for (int im = 0; im < 4; im++) {
#pragma unroll
        for (int h2 = 0; h2 < 2; h2++) {
            int row = wm + im * 16 + (lane >> 2) + h2 * 8;
            float xj = xxA[row];
#pragma unroll
            for (int in = 0; in < 4; in++) {
                int n = wn + in * 8 + (lane & 3) * 2;
                float g0 = acc[im][in][h2 * 2 + 0];
                float g1 = acc[im][in][h2 * 2 + 1];
                float v0 = sqrtf(fmaxf((xj + xxB[n])     - 2.0f * g0, 0.0f));
                float v1 = sqrtf(fmaxf((xj + xxB[n + 1]) - 2.0f * g1, 0.0f));
                *(float2*)&g_dist[((size_t)(bofs + j0 + row)) * NN + i0 + n] = make_float2(v0, v1);
                if (!diag) {
                    smemT[(n)     * T_PITCH + row] = v0;
                    smemT[(n + 1) * T_PITCH + row] = v1;
                }
            }
        }
    }

    if (!diag) {
        __syncthreads();
#pragma unroll
        for (int q = 0; q < 16; q++) {
            int fid = tid + 256 * q;
            int nrow = fid >> 5, f4 = fid & 31;
            float4 val = *(float4*)&smemT[nrow * T_PITCH + f4 * 4];
            *(float4*)&g_dist[((size_t)(bofs + i0 + nrow)) * NN + j0 + f4 * 4] = val;
        }
    }
}

// ---------------------------------------------------------------------------
// Kernel 3: per-row top-16 smallest (stable tie -> lower index), write row.
// ---------------------------------------------------------------------------
__device__ __forceinline__ void cmin(float& v, int& i, float v2, int i2) {
    if (v2 < v || (v2 == v && i2 < i)) { v = v2; i = i2; }
}

__global__ __launch_bounds__(256) void topk_kernel(float* __restrict__ out) {
    int row = blockIdx.x;
    int tid = threadIdx.x;
    int lane = tid & 31;
    int wrp  = tid >> 5;

    __shared__ float vals[NN];
    __shared__ float wv[8];
    __shared__ int   wi[8];
    __shared__ int   widx[16];

    const float* drow = g_dist + (size_t)row * NN;
#pragma unroll
    for (int q = 0; q < 2; q++)
        *(float4*)&vals[tid * 8 + q * 4] = *(const float4*)(drow + tid * 8 + q * 4);
    __syncthreads();

    for (int it = 0; it < 16; it++) {
        float lv = FLT_MAX;
        int   li = NN;
#pragma unroll
        for (int q = 0; q < 8; q++) cmin(lv, li, vals[tid * 8 + q], tid * 8 + q);
#pragma unroll
        for (int off = 16; off; off >>= 1) {
            float ov = __shfl_down_sync(0xffffffffu, lv, off);
            int   oi = __shfl_down_sync(0xffffffffu, li, off);
            cmin(lv, li, ov, oi);
        }
        if (lane == 0) { wv[wrp] = lv; wi[wrp] = li; }
        __syncthreads();
        if (tid == 0) {
            float bv = wv[0]; int bi = wi[0];
#pragma unroll
            for (int w = 1; w < 8; w++) cmin(bv, bi, wv[w], wi[w]);
            widx[it] = bi;
            vals[bi] = FLT_MAX;
        }
        __syncthreads();
    }

#pragma unroll
    for (int q = 0; q < 2; q++)
        *(float4*)&vals[tid * 8 + q * 4] = make_float4(0.f, 0.f, 0.f, 0.f);
    __syncthreads();
    if (tid < 16) vals[widx[tid]] = 1.0f;
    __syncthreads();

    float* orow = out + (size_t)row * NN;
#pragma unroll
    for (int q = 0; q < 2; q++)
        *(float4*)(orow + tid * 8 + q * 4) = *(float4*)&vals[tid * 8 + q * 4];
}

// ---------------------------------------------------------------------------
extern "C" void kernel_launch(void* const* d_in, const int* in_sizes, int n_in,
                              void* d_out, int out_size) {
    const float* put = (const float*)d_in[0];
    float* out = (float*)d_out;

    cudaFuncSetAttribute(dist_mma_kernel, cudaFuncAttributeMaxDynamicSharedMemorySize, SM_TOTAL);

    split_kernel<<<(BB * NN * DD) / (256 * 4), 256>>>(put);
    xx_kernel<<<(BB * NN) / 8, 256>>>(put);
    dim3 grid(NN / 128, NN / 128, BB);
    dist_mma_kernel<<<grid, 256, SM_TOTAL>>>();
    topk_kernel<<<BB * NN, 256>>>(out);
}

// round 5
// speedup vs baseline: 1.7300x; 1.7300x over previous
#include <cuda_runtime.h>
#include <cuda_fp16.h>
#include <float.h>
#include <math.h>
#include <cstdint>

#define BB 8
#define NN 2048
#define DD 512

// ---------------------------------------------------------------------------
// Scratch (__device__ globals only — allocation-free contract)
// ---------------------------------------------------------------------------
__device__ float g_xx[BB * NN];
__device__ float g_dist[(size_t)BB * NN * NN];          // 134 MB
__device__ __half g_sp[2][(size_t)BB * NN * DD];        // h / l fp16 splits, 32 MB

__device__ __forceinline__ uint32_t smem_u32(const void* p) {
    uint32_t a;
    asm("{ .reg .u64 t; cvta.to.shared.u64 t, %1; cvt.u32.u64 %0, t; }" : "=r"(a) : "l"(p));
    return a;
}

#define LDSM4(r0, r1, r2, r3, addr) \
    asm volatile("ldmatrix.sync.aligned.m8n8.x4.shared.b16 {%0,%1,%2,%3}, [%4];" \
                 : "=r"(r0), "=r"(r1), "=r"(r2), "=r"(r3) : "r"(addr))

#define MMA16816(c, a, b0, b1) \
    asm volatile("mma.sync.aligned.m16n8k16.row.col.f32.f16.f16.f32 " \
                 "{%0,%1,%2,%3}, {%4,%5,%6,%7}, {%8,%9}, {%0,%1,%2,%3};" \
                 : "+f"((c)[0]), "+f"((c)[1]), "+f"((c)[2]), "+f"((c)[3]) \
                 : "r"((a)[0]), "r"((a)[1]), "r"((a)[2]), "r"((a)[3]), "r"(b0), "r"(b1))

#define CP_ASYNC16(dst, src) \
    asm volatile("cp.async.cg.shared.global [%0], [%1], 16;" :: "r"(dst), "l"(src))
#define CP_COMMIT() asm volatile("cp.async.commit_group;" ::: "memory")

// ---------------------------------------------------------------------------
// Kernel 0: fp16 2-word split of put  (x = h + l exactly to 2^-22)
// ---------------------------------------------------------------------------
__global__ __launch_bounds__(256) void split_kernel(const float* __restrict__ put) {
    size_t i4 = ((size_t)blockIdx.x * 256 + threadIdx.x) * 4;
    float4 v = *(const float4*)(put + i4);
    float x[4] = {v.x, v.y, v.z, v.w};
    __half h[4], l[4];
#pragma unroll
    for (int q = 0; q < 4; q++) {
        h[q] = __float2half(x[q]);
        l[q] = __float2half(x[q] - __half2float(h[q]));
    }
    *(uint2*)(&g_sp[0][i4]) = *(uint2*)h;
    *(uint2*)(&g_sp[1][i4]) = *(uint2*)l;
}

// ---------------------------------------------------------------------------
// Kernel 1: row squared norms (fp32 exact)
// ---------------------------------------------------------------------------
__global__ __launch_bounds__(256) void xx_kernel(const float* __restrict__ put) {
    int row  = blockIdx.x * 8 + (threadIdx.x >> 5);
    int lane = threadIdx.x & 31;
    const float* p = put + (size_t)row * DD;
    float s = 0.f;
#pragma unroll
    for (int f = 0; f < 4; f++) {
        float4 v = *(const float4*)(p + f * 128 + lane * 4);
        s = fmaf(v.x, v.x, s); s = fmaf(v.y, v.y, s);
        s = fmaf(v.z, v.z, s); s = fmaf(v.w, v.w, s);
    }
#pragma unroll
    for (int off = 16; off; off >>= 1) s += __shfl_xor_sync(0xffffffffu, s, off);
    if (lane == 0) g_xx[row] = s;
}

// ---------------------------------------------------------------------------
// Kernel 2: distance tiles via classic mma.sync fp16 3-pass split GEMM.
// (unchanged from R4 — passing, rel_err 0.0)
// ---------------------------------------------------------------------------
#define PITCH_H 40
#define TILE_B  (128 * PITCH_H * 2)
#define BUF_B   (4 * TILE_B)
#define XX_OFF  (2 * BUF_B)
#define SM_TOTAL (XX_OFF + 1024)
#define T_PITCH 136

__global__ __launch_bounds__(256, 1) void dist_mma_kernel() {
    int bx = blockIdx.x, by = blockIdx.y, b = blockIdx.z;
    if (by > bx) return;
    bool diag = (bx == by);

    extern __shared__ char smem[];
    uint32_t sbase = smem_u32(smem);
    int tid  = threadIdx.x;
    int lane = tid & 31;
    int wid  = tid >> 5;

    int j0 = by * 128, i0 = bx * 128, bofs = b * NN;

    float* xxA = (float*)(smem + XX_OFF);
    float* xxB = (float*)(smem + XX_OFF + 512);
    if (tid < 128) {
        xxA[tid] = g_xx[bofs + j0 + tid];
        xxB[tid] = g_xx[bofs + i0 + tid];
    }

    int fr   = (tid >> 2);
    int fck  = tid & 3;
    auto fill = [&](int buf, int kt) {
#pragma unroll
        for (int q = 0; q < 8; q++) {
            int rr   = fr + 64 * (q & 1);
            int tile = q >> 1;
            int word = tile & 1;
            int grow = (tile < 2 ? j0 : i0) + rr;
            const __half* src = &g_sp[word][(size_t)(bofs + grow) * DD + kt * 32 + fck * 8];
            uint32_t dst = sbase + buf * BUF_B + tile * TILE_B + rr * (PITCH_H * 2) + fck * 16;
            CP_ASYNC16(dst, src);
        }
    };

    int wm = (wid >> 2) * 64;
    int wn = (wid & 3) * 32;

    float acc[4][4][4];
#pragma unroll
    for (int im = 0; im < 4; im++)
#pragma unroll
        for (int in = 0; in < 4; in++)
#pragma unroll
            for (int q = 0; q < 4; q++) acc[im][in][q] = 0.f;

    fill(0, 0);
    CP_COMMIT();

    int arow = lane & 15;
    int acol = (lane >> 4) * 8;
    int brow = (lane & 7) + ((lane >> 4) << 3);
    int bcol = ((lane >> 3) & 1) * 8;

    for (int kt = 0; kt < 16; kt++) {
        if (kt < 15) { fill((kt + 1) & 1, kt + 1); CP_COMMIT(); }
        if (kt < 15) asm volatile("cp.async.wait_group 1;" ::: "memory");
        else         asm volatile("cp.async.wait_group 0;" ::: "memory");
        __syncthreads();

        uint32_t base = sbase + (kt & 1) * BUF_B;
#pragma unroll
        for (int kc = 0; kc < 2; kc++) {
            int kofs = kc * 16;
            uint32_t ah[4][4], al[4][4];
#pragma unroll
            for (int im = 0; im < 4; im++) {
                uint32_t off = (uint32_t)((wm + im * 16 + arow) * (PITCH_H * 2) + (kofs + acol) * 2);
                LDSM4(ah[im][0], ah[im][1], ah[im][2], ah[im][3], base + 0 * TILE_B + off);
                LDSM4(al[im][0], al[im][1], al[im][2], al[im][3], base + 1 * TILE_B + off);
            }
            uint32_t bh[8], bl[8];
#pragma unroll
            for (int bp = 0; bp < 2; bp++) {
                uint32_t off = (uint32_t)((wn + bp * 16 + brow) * (PITCH_H * 2) + (kofs + bcol) * 2);
                LDSM4(bh[bp*4+0], bh[bp*4+1], bh[bp*4+2], bh[bp*4+3], base + 2 * TILE_B + off);
                LDSM4(bl[bp*4+0], bl[bp*4+1], bl[bp*4+2], bl[bp*4+3], base + 3 * TILE_B + off);
            }
#pragma unroll
            for (int im = 0; im < 4; im++)
#pragma unroll
                for (int in = 0; in < 4; in++) {
                    MMA16816(acc[im][in], ah[im], bh[in*2], bh[in*2+1]);
                    MMA16816(acc[im][in], ah[im], bl[in*2], bl[in*2+1]);
                    MMA16816(acc[im][in], al[im], bh[in*2], bh[in*2+1]);
                }
        }
        __syncthreads();
    }

    float* smemT = (float*)smem;

#pragma unroll
    for (int im = 0; im < 4; im++) {
#pragma unroll
        for (int h2 = 0; h2 < 2; h2++) {
            int row = wm + im * 16 + (lane >> 2) + h2 * 8;
            float xj = xxA[row];
#pragma unroll
            for (int in = 0; in < 4; in++) {
                int n = wn + in * 8 + (lane & 3) * 2;
                float g0 = acc[im][in][h2 * 2 + 0];
                float g1 = acc[im][in][h2 * 2 + 1];
                float v0 = sqrtf(fmaxf((xj + xxB[n])     - 2.0f * g0, 0.0f));
                float v1 = sqrtf(fmaxf((xj + xxB[n + 1]) - 2.0f * g1, 0.0f));
                *(float2*)&g_dist[((size_t)(bofs + j0 + row)) * NN + i0 + n] = make_float2(v0, v1);
                if (!diag) {
                    smemT[(n)     * T_PITCH + row] = v0;
                    smemT[(n + 1) * T_PITCH + row] = v1;
                }
            }
        }
    }

    if (!diag) {
        __syncthreads();
#pragma unroll
        for (int q = 0; q < 16; q++) {
            int fid = tid + 256 * q;
            int nrow = fid >> 5, f4 = fid & 31;
            float4 val = *(float4*)&smemT[nrow * T_PITCH + f4 * 4];
            *(float4*)&g_dist[((size_t)(bofs + i0 + nrow)) * NN + j0 + f4 * 4] = val;
        }
    }
}

// ---------------------------------------------------------------------------
// Kernel 3: per-row top-16 via exact 2-level radix select (bits [31:16]).
// Positive floats: uint bit order == float order. Stable (val, idx) tie-break.
// ---------------------------------------------------------------------------
#define CAND_CAP 512

__device__ __forceinline__ void cmin3(uint32_t& v, uint32_t& i, uint32_t& j,
                                      uint32_t v2, uint32_t i2, uint32_t j2) {
    if (v2 < v || (v2 == v && i2 < i)) { v = v2; i = i2; j = j2; }
}

__global__ __launch_bounds__(256) void topk_kernel(float* __restrict__ out) {
    int row  = blockIdx.x;
    int tid  = threadIdx.x;
    int lane = tid & 31;

    __shared__ uint32_t hist[256];
    __shared__ uint32_t s_b0, s_c0, s_clt;
    __shared__ uint32_t s_nsure, s_ncand;
    __shared__ uint32_t s_P;
    __shared__ uint32_t sure_idx[16];
    __shared__ uint32_t cand_v[CAND_CAP];
    __shared__ uint32_t cand_i[CAND_CAP];
    __shared__ uint32_t widx[16];

    // load row (as uint bits)
    const float* drow = g_dist + (size_t)row * NN;
    uint32_t v[8];
    {
        float4 a = *(const float4*)(drow + tid * 8);
        float4 b = *(const float4*)(drow + tid * 8 + 4);
        v[0] = __float_as_uint(a.x); v[1] = __float_as_uint(a.y);
        v[2] = __float_as_uint(a.z); v[3] = __float_as_uint(a.w);
        v[4] = __float_as_uint(b.x); v[5] = __float_as_uint(b.y);
        v[6] = __float_as_uint(b.z); v[7] = __float_as_uint(b.w);
    }

    hist[tid] = 0;
    if (tid == 0) { s_nsure = 0; s_ncand = 0; }
    __syncthreads();

    // ---- level 0: hist over bits [31:24], warp-aggregated atomics ----
#pragma unroll
    for (int q = 0; q < 8; q++) {
        uint32_t bin = v[q] >> 24;
        uint32_t mask = __match_any_sync(0xffffffffu, bin);
        if (lane == (__ffs(mask) - 1)) atomicAdd(&hist[bin], __popc(mask));
    }
    __syncthreads();

    // warp 0: find bin containing the 16th smallest
    if (tid < 32) {
        uint32_t loc[8], s = 0;
#pragma unroll
        for (int i = 0; i < 8; i++) { loc[i] = hist[tid * 8 + i]; s += loc[i]; }
        uint32_t incl = s;
#pragma unroll
        for (int off = 1; off < 32; off <<= 1) {
            uint32_t t2 = __shfl_up_sync(0xffffffffu, incl, off);
            if (lane >= off) incl += t2;
        }
        uint32_t run = incl - s;   // exclusive prefix
#pragma unroll
        for (int i = 0; i < 8; i++) {
            if (run < 16u && 16u <= run + loc[i]) { s_b0 = tid * 8 + i; s_c0 = run; }
            run += loc[i];
        }
    }
    __syncthreads();
    uint32_t b0 = s_b0, c0 = s_c0;

    hist[tid] = 0;
    __syncthreads();

    // ---- level 1: hist over bits [23:16] for values whose top byte == b0 ----
#pragma unroll
    for (int q = 0; q < 8; q++) {
        bool act = ((v[q] >> 24) == b0);
        uint32_t bin = act ? ((v[q] >> 16) & 255u) : (256u + lane);  // unique dummies
        uint32_t mask = __match_any_sync(0xffffffffu, bin);
        if (act && lane == (__ffs(mask) - 1)) atomicAdd(&hist[bin], __popc(mask));
    }
    __syncthreads();

    uint32_t k1 = 16u - c0;
    if (tid < 32) {
        uint32_t loc[8], s = 0;
#pragma unroll
        for (int i = 0; i < 8; i++) { loc[i] = hist[tid * 8 + i]; s += loc[i]; }
        uint32_t incl = s;
#pragma unroll
        for (int off = 1; off < 32; off <<= 1) {
            uint32_t t2 = __shfl_up_sync(0xffffffffu, incl, off);
            if (lane >= off) incl += t2;
        }
        uint32_t run = incl - s;
#pragma unroll
        for (int i = 0; i < 8; i++) {
            if (run < k1 && k1 <= run + loc[i]) {
                s_P   = (b0 << 8) | (uint32_t)(tid * 8 + i);
                s_clt = c0 + run;
            }
            run += loc[i];
        }
    }
    __syncthreads();
    uint32_t P = s_P, clt = s_clt, m = 16u - clt;

    // ---- gather: sure (prefix < P) and candidates (prefix == P) ----
#pragma unroll
    for (int q = 0; q < 8; q++) {
        uint32_t hi = v[q] >> 16;
        if (hi < P) {
            uint32_t p = atomicAdd(&s_nsure, 1u);
            sure_idx[p] = tid * 8 + q;
        } else if (hi == P) {
            uint32_t p = atomicAdd(&s_ncand, 1u);
            if (p < CAND_CAP) { cand_v[p] = v[q]; cand_i[p] = tid * 8 + q; }
        }
    }
    __syncthreads();

    // ---- warp 0: m stable-min rounds over the small candidate list ----
    if (tid < 32) {
        uint32_t n = min(s_ncand, (uint32_t)CAND_CAP);
        for (uint32_t it = 0; it < m; it++) {
            uint32_t bv = 0xffffffffu, bi = 0xffffffffu, bj = 0xffffffffu;
            for (uint32_t j = lane; j < n; j += 32)
                cmin3(bv, bi, bj, cand_v[j], cand_i[j], j);
#pragma unroll
            for (int off = 16; off; off >>= 1) {
                uint32_t ov = __shfl_down_sync(0xffffffffu, bv, off);
                uint32_t oi = __shfl_down_sync(0xffffffffu, bi, off);
                uint32_t oj = __shfl_down_sync(0xffffffffu, bj, off);
                cmin3(bv, bi, bj, ov, oi, oj);
            }
            if (lane == 0) {
                widx[it] = bi;
                cand_v[bj] = 0xffffffffu;
                cand_i[bj] = 0xffffffffu;
            }
            __syncwarp();
        }
    }
    __syncthreads();

    // ---- write: zero row, then scatter the 16 ones ----
    float* orow = out + (size_t)row * NN;
    float4 z = make_float4(0.f, 0.f, 0.f, 0.f);
    *(float4*)(orow + tid * 8)     = z;
    *(float4*)(orow + tid * 8 + 4) = z;
    __syncthreads();
    if (tid < clt)                    orow[sure_idx[tid]]  = 1.0f;
    if (tid >= 32 && tid < 32 + m)    orow[widx[tid - 32]] = 1.0f;
}

// ---------------------------------------------------------------------------
extern "C" void kernel_launch(void* const* d_in, const int* in_sizes, int n_in,
                              void* d_out, int out_size) {
    const float* put = (const float*)d_in[0];
    float* out = (float*)d_out;

    cudaFuncSetAttribute(dist_mma_kernel, cudaFuncAttributeMaxDynamicSharedMemorySize, SM_TOTAL);

    split_kernel<<<(BB * NN * DD) / (256 * 4), 256>>>(put);
    xx_kernel<<<(BB * NN) / 8, 256>>>(put);
    dim3 grid(NN / 128, NN / 128, BB);
    dist_mma_kernel<<<grid, 256, SM_TOTAL>>>();
    topk_kernel<<<BB * NN, 256>>>(out);
}